// round 14
// baseline (speedup 1.0000x reference)
#include <cuda_runtime.h>
#include <cuda_bf16.h>
#include <cstdint>

#define D_DIM   256
#define NPATCH  16384
#define VOCAB   4096

#define NVT     16          // vocab tiles of 256 rows
#define VTN     256
#define CHM     64          // patches per chunk
#define NGRP    9           // grid = 144
#define NCHUNK  (NPATCH / CHM)   // 256

#define B_BYTES (VTN * 512)              // 131072 (vocab tile bf16, full K)
#define A_STAGE (CHM * 512)              // 32768
#define SMEM_BYTES (B_BYTES + 3 * A_STAGE)  // 229376

#define BIAS    512.0f
#define THR     2.5f

__device__ float         g_v2[VOCAB];
__device__ __nv_bfloat16 g_pb[NPATCH * D_DIM];
__device__ __nv_bfloat16 g_vb[VOCAB * D_DIM];
__device__ uint32_t      g_cand[(size_t)NPATCH * 256];   // [patch][vt*16+wn*2+(t>>1)] best-1 key

#define CP_ASYNC16(dst, src) \
    asm volatile("cp.async.cg.shared.global [%0], [%1], 16;" :: "r"((uint32_t)(dst)), "l"(src))
#define CP_COMMIT() asm volatile("cp.async.commit_group;" ::: "memory")

__device__ __forceinline__ void mma16(float* c, uint32_t a0, uint32_t a1, uint32_t a2, uint32_t a3,
                                      uint32_t b0, uint32_t b1) {
    asm("mma.sync.aligned.m16n8k16.row.col.f32.bf16.bf16.f32 "
        "{%0,%1,%2,%3}, {%4,%5,%6,%7}, {%8,%9}, {%0,%1,%2,%3};"
        : "+f"(c[0]), "+f"(c[1]), "+f"(c[2]), "+f"(c[3])
        : "r"(a0), "r"(a1), "r"(a2), "r"(a3), "r"(b0), "r"(b1));
}

// biased-positive key: raw float bits order directly; vocab idx in low 12 bits
__device__ __forceinline__ uint32_t fkey(float sb, int n) {
    return (__float_as_uint(sb) & 0xFFFFF000u) | (uint32_t)n;
}

// within a 32-k block: lane t's 16B covers both k16 groups (proven layout)
__device__ __forceinline__ int perm32(int k) {
    return ((k & 7) >> 1) * 8 + ((k >> 4) & 1) * 4 + ((k >> 3) & 1) * 2 + (k & 1);
}

// ---------------------------------------------------------------------------
// prep: vocab -> bf16 (permuted) + v2, one warp per row
// ---------------------------------------------------------------------------
__global__ void vocab_prep_kernel(const float* __restrict__ vocab) {
    const int v = blockIdx.x * 8 + (threadIdx.x >> 5);
    const int lane = threadIdx.x & 31;
    const float* row = vocab + (size_t)v * D_DIM;
    float s = 0.f;
#pragma unroll
    for (int e = 0; e < 2; e++) {
        const float4 x = *(const float4*)(row + lane * 8 + e * 4);
        s += x.x * x.x + x.y * x.y + x.z * x.z + x.w * x.w;
        const int d0 = lane * 8 + e * 4;
#pragma unroll
        for (int q = 0; q < 4; q++) {
            const int d = d0 + q;
            const float xv = q == 0 ? x.x : q == 1 ? x.y : q == 2 ? x.z : x.w;
            g_vb[v * D_DIM + (d & ~31) + perm32(d & 31)] = __float2bfloat16_rn(xv);
        }
    }
#pragma unroll
    for (int o = 16; o > 0; o >>= 1) s += __shfl_xor_sync(0xffffffffu, s, o);
    if (lane == 0) g_v2[v] = s;
}

__global__ void patchify_bf_kernel(const float* __restrict__ images,
                                   float* __restrict__ patches, int total) {
    int idx = blockIdx.x * blockDim.x + threadIdx.x;
    if (idx >= total) return;
    int d = idx & 255, n = (idx >> 8) & 255, b = idx >> 16;
    int ph = n >> 4, pw = n & 15, i = d >> 4, j = d & 15;
    float x = images[(b << 16) + ((ph * 16 + i) << 8) + pw * 16 + j];
    patches[idx] = x;
    g_pb[(idx & ~255) + (d & ~31) + perm32(d & 31)] = __float2bfloat16_rn(x);
}

// ---------------------------------------------------------------------------
// vq: bf16 mma, vocab tile resident, 3-stage A pipeline, half-CTA barriers,
//     best1 per 16-col group, software-pipelined kb loop (hoisted B frags,
//     prefetched next-kb A frags)
// ---------------------------------------------------------------------------
__global__ __launch_bounds__(512, 1)
void vq_kernel() {
    extern __shared__ char sm[];
    const uint32_t smem = (uint32_t)__cvta_generic_to_shared(sm);
    const uint32_t smA = smem + B_BYTES;

    const int tid  = threadIdx.x;
    const int lane = tid & 31;
    const int wid  = tid >> 5;
    const int g    = lane >> 2;
    const int t    = lane & 3;
    const int wm   = wid >> 3;           // warps 0-7 rows 0-31 (they also WRITE those rows)
    const int wn   = wid & 7;            // 8 n-warps (32 vocab cols)

    const int vt  = blockIdx.x & 15;
    const int grp = blockIdx.x >> 4;
    const int c0  = (grp * NCHUNK) / NGRP;
    const int c1  = ((grp + 1) * NCHUNK) / NGRP;

    // ---- prologue: resident B tile + A chunk c0 (one commit group) ----
    {
        const int rB = tid >> 1, hB = tid & 1;
        const __nv_bfloat16* srcB = g_vb + (size_t)(vt * VTN + rB) * D_DIM + hB * 128;
        const uint32_t dB = smem + rB * 512;
        const uint32_t swB = (uint32_t)(rB & 7) << 2;
#pragma unroll
        for (int uu = 0; uu < 16; uu++) {
            const int u = hB * 16 + uu;
            CP_ASYNC16(dB + (((uint32_t)u ^ swB) << 4), srcB + uu * 8);
        }
        const int rA = tid >> 3, qA = tid & 7;   // warp w writes rows 4w..4w+3
        const __nv_bfloat16* srcA = g_pb + (size_t)(c0 * CHM + rA) * D_DIM + qA * 32;
        const uint32_t swA = (uint32_t)(rA & 7) << 2;
#pragma unroll
        for (int uu = 0; uu < 4; uu++) {
            const int u = qA * 4 + uu;
            CP_ASYNC16(smA + rA * 512 + (((uint32_t)u ^ swA) << 4), srcA + uu * 8);
        }
        CP_COMMIT();
    }

    // biased v2 for owned columns
    float v2b[8];
#pragma unroll
    for (int j = 0; j < 4; j++)
#pragma unroll
        for (int e = 0; e < 2; e++)
            v2b[j * 2 + e] = __ldg(g_v2 + vt * VTN + wn * 32 + j * 8 + 2 * t + e) + BIAS;

    const int gi = vt * 16 + wn * 2 + (t >> 1);     // merged group index (16-col groups)
    const int barid = 1 + wm;                        // half-CTA named barrier
    const int arow0 = wm * 32 + g;                   // A row base for this lane

    // full-CTA sync once: B tile written by everyone, read by everyone
    asm volatile("cp.async.wait_group 0;" ::: "memory");
    __syncthreads();

#define LOAD_AF(dst, Ab, kb) do { \
        const uint32_t _ao = (uint32_t)(((((kb) ^ g) << 2) | t) << 4); \
        _Pragma("unroll") \
        for (int _i = 0; _i < 2; _i++) \
            _Pragma("unroll") \
            for (int _h = 0; _h < 2; _h++) \
                (dst)[_i][_h] = *(const uint4*)((Ab) + (arow0 + _i * 16 + _h * 8) * 512 + _ao); \
    } while (0)

    int s_nxt = 1;                  // stage of chunk c+1
#pragma unroll 1
    for (int c = c0; c < c1; c++) {
        const int s_cur = (s_nxt + 2) % 3;
        if (c + 1 < c1) {
            const int rA = tid >> 3, qA = tid & 7;
            const __nv_bfloat16* srcA = g_pb + (size_t)((c + 1) * CHM + rA) * D_DIM + qA * 32;
            const uint32_t dA = smA + s_nxt * A_STAGE + rA * 512;
            const uint32_t swA = (uint32_t)(rA & 7) << 2;
#pragma unroll
            for (int uu = 0; uu < 4; uu++) {
                const int u = qA * 4 + uu;
                CP_ASYNC16(dA + (((uint32_t)u ^ swA) << 4), srcA + uu * 8);
            }
            CP_COMMIT();
            asm volatile("cp.async.wait_group 1;" ::: "memory");
        } else {
            asm volatile("cp.async.wait_group 0;" ::: "memory");
        }
        // half-CTA barrier: writers of rows [wm*32, wm*32+32) == readers of same
        asm volatile("bar.sync %0, %1;" :: "r"(barid), "r"(256) : "memory");

        const char* Ab = sm + B_BYTES + s_cur * A_STAGE;
        float acc[2][4][4];
#pragma unroll
        for (int i = 0; i < 2; i++)
#pragma unroll
            for (int j = 0; j < 4; j++)
#pragma unroll
                for (int e = 0; e < 4; e++) acc[i][j][e] = 0.f;

        // software-pipelined kb loop
        uint4 afc[2][2], afn[2][2], bfv[4];
        LOAD_AF(afc, Ab, 0);
#pragma unroll
        for (int kb = 0; kb < 8; kb++) {
            const uint32_t aoff = (uint32_t)((((kb ^ g) << 2) | t) << 4);
            // hoist all 4 B fragments for this kb
#pragma unroll
            for (int j = 0; j < 4; j++) {
                const int n = wn * 32 + j * 8 + g;      // n & 7 == g
                bfv[j] = *(const uint4*)(sm + n * 512 + aoff);
            }
            // prefetch next kb's A fragments while this kb's MMAs run
            if (kb < 7) LOAD_AF(afn, Ab, kb + 1);
#pragma unroll
            for (int j = 0; j < 4; j++) {
#pragma unroll
                for (int i = 0; i < 2; i++) {
                    float* cacc = acc[i][j];
                    mma16(cacc, afc[i][0].x, afc[i][1].x, afc[i][0].y, afc[i][1].y,
                          bfv[j].x, bfv[j].y);
                    mma16(cacc, afc[i][0].z, afc[i][1].z, afc[i][0].w, afc[i][1].w,
                          bfv[j].z, bfv[j].w);
                }
            }
#pragma unroll
            for (int i = 0; i < 2; i++)
#pragma unroll
                for (int h = 0; h < 2; h++)
                    afc[i][h] = afn[i][h];
        }

        // epilogue: per-lane best1 over 8 cols per row-slot, then t-pair merge
        uint32_t k1[4];
#pragma unroll
        for (int sl = 0; sl < 4; sl++) k1[sl] = ~0u;
#pragma unroll
        for (int j = 0; j < 4; j++) {
            const int nn = vt * VTN + wn * 32 + j * 8 + 2 * t;
#pragma unroll
            for (int i = 0; i < 2; i++) {
                const uint32_t ka = min(fkey(fmaf(acc[i][j][0], -2.f, v2b[j * 2 + 0]), nn),
                                        fkey(fmaf(acc[i][j][1], -2.f, v2b[j * 2 + 1]), nn + 1));
                const uint32_t kb_ = min(fkey(fmaf(acc[i][j][2], -2.f, v2b[j * 2 + 0]), nn),
                                         fkey(fmaf(acc[i][j][3], -2.f, v2b[j * 2 + 1]), nn + 1));
                k1[i * 2 + 0] = min(k1[i * 2 + 0], ka);
                k1[i * 2 + 1] = min(k1[i * 2 + 1], kb_);
            }
        }
#pragma unroll
        for (int sl = 0; sl < 4; sl++)
            k1[sl] = min(k1[sl], __shfl_xor_sync(0xffffffffu, k1[sl], 1));
        if ((t & 1) == 0) {
#pragma unroll
            for (int i = 0; i < 2; i++)
#pragma unroll
                for (int h = 0; h < 2; h++) {
                    const int row = c * CHM + wm * 32 + i * 16 + h * 8 + g;
                    g_cand[(size_t)row * 256 + gi] = k1[i * 2 + h];
                }
        }

        s_nxt = s_nxt + 1 == 3 ? 0 : s_nxt + 1;
    }
}

// ---------------------------------------------------------------------------
// exact fp32 rescue: one WARP per patch, 256 coalesced best1 keys, coop dots
// ---------------------------------------------------------------------------
__global__ __launch_bounds__(256)
void rescue_kernel(const float* __restrict__ patches,
                   const float* __restrict__ vocab,
                   float* __restrict__ tokens) {
    const int p    = (blockIdx.x * 256 + threadIdx.x) >> 5;
    const int lane = threadIdx.x & 31;
    if (p >= NPATCH) return;

    const uint4* cp4 = (const uint4*)(g_cand + (size_t)p * 256);   // 64 uint4
    const uint4 kk0 = cp4[lane];
    const uint4 kk1 = cp4[32 + lane];
    const uint32_t keys[8] = {kk0.x, kk0.y, kk0.z, kk0.w, kk1.x, kk1.y, kk1.z, kk1.w};

    uint32_t kmin = ~0u;
#pragma unroll
    for (int r = 0; r < 8; r++) kmin = min(kmin, keys[r]);
#pragma unroll
    for (int o = 16; o > 0; o >>= 1)
        kmin = min(kmin, __shfl_xor_sync(0xffffffffu, kmin, o));
    const float fthr = __uint_as_float(kmin & 0xFFFFF000u) + THR;
    const uint32_t thrk = __float_as_uint(fthr) | 0xFFFu;

    const float* pp = patches + (size_t)p * D_DIM;
    const float4 pa = *(const float4*)(pp + lane * 8);
    const float4 pb = *(const float4*)(pp + lane * 8 + 4);

    float bestv = 3.4e38f;
    int   besti = 0x7FFFFFFF;
#pragma unroll
    for (int r = 0; r < 8; r++) {
        unsigned mask = __ballot_sync(0xffffffffu, keys[r] <= thrk);
        while (mask) {
            const int src = __ffs(mask) - 1;
            mask &= mask - 1;
            const int vi = (int)(__shfl_sync(0xffffffffu, keys[r], src) & 0xFFFu);
            const float* vp = vocab + (size_t)vi * D_DIM;
            const float4 va = *(const float4*)(vp + lane * 8);
            const float4 vb = *(const float4*)(vp + lane * 8 + 4);
            float d = pa.x * va.x + pa.y * va.y + pa.z * va.z + pa.w * va.w
                    + pb.x * vb.x + pb.y * vb.y + pb.z * vb.z + pb.w * vb.w;
#pragma unroll
            for (int o = 16; o > 0; o >>= 1)
                d += __shfl_xor_sync(0xffffffffu, d, o);
            const float se = __ldg(&g_v2[vi]) - 2.f * d;
            if (se < bestv || (se == bestv && vi < besti)) { bestv = se; besti = vi; }
        }
    }
    if (lane == 0) tokens[p] = (float)besti;
}

// ---------------------------------------------------------------------------
extern "C" void kernel_launch(void* const* d_in, const int* in_sizes, int n_in,
                              void* d_out, int out_size) {
    const float* images = (const float*)d_in[0];   // [64, 256, 256]
    const float* vocab  = (const float*)d_in[1];   // [4096, 256]
    float* out = (float*)d_out;

    const int npix = in_sizes[0];                  // 4194304
    const int nvoc = in_sizes[1];                  // 1048576
    const int V = nvoc / D_DIM;                    // 4096

    float* patches = out;
    float* tokens  = out + npix;

    vocab_prep_kernel<<<V / 8, 256>>>(vocab);
    patchify_bf_kernel<<<(npix + 255) / 256, 256>>>(images, patches, npix);

    cudaFuncSetAttribute(vq_kernel, cudaFuncAttributeMaxDynamicSharedMemorySize, SMEM_BYTES);
    vq_kernel<<<NVT * NGRP, 512, SMEM_BYTES>>>();

    rescue_kernel<<<(NPATCH * 32) / 256, 256>>>(patches, vocab, tokens);
}

// round 15
// speedup vs baseline: 1.0352x; 1.0352x over previous
#include <cuda_runtime.h>
#include <cuda_bf16.h>
#include <cstdint>

#define D_DIM   256
#define NPATCH  16384
#define VOCAB   4096

#define NVT     16          // vocab tiles of 256 rows
#define VTN     256
#define CHM     64          // patches per chunk
#define NGRP    9           // grid = 144
#define NCHUNK  (NPATCH / CHM)   // 256

#define B_BYTES (VTN * 512)              // 131072 (vocab tile bf16, full K)
#define A_STAGE (CHM * 512)              // 32768
#define SMEM_BYTES (B_BYTES + 3 * A_STAGE)  // 229376

#define BIAS    512.0f
#define THR     2.5f

__device__ float         g_v2[VOCAB];
__device__ __nv_bfloat16 g_pb[NPATCH * D_DIM];
__device__ __nv_bfloat16 g_vb[VOCAB * D_DIM];
__device__ uint32_t      g_cand[(size_t)NPATCH * 256];   // [patch][vt*16+wn*2+(t>>1)] best-1 key

#define CP_ASYNC16(dst, src) \
    asm volatile("cp.async.cg.shared.global [%0], [%1], 16;" :: "r"((uint32_t)(dst)), "l"(src))
#define CP_COMMIT() asm volatile("cp.async.commit_group;" ::: "memory")

__device__ __forceinline__ void mma16(float* c, uint32_t a0, uint32_t a1, uint32_t a2, uint32_t a3,
                                      uint32_t b0, uint32_t b1) {
    asm("mma.sync.aligned.m16n8k16.row.col.f32.bf16.bf16.f32 "
        "{%0,%1,%2,%3}, {%4,%5,%6,%7}, {%8,%9}, {%0,%1,%2,%3};"
        : "+f"(c[0]), "+f"(c[1]), "+f"(c[2]), "+f"(c[3])
        : "r"(a0), "r"(a1), "r"(a2), "r"(a3), "r"(b0), "r"(b1));
}

// biased-positive key: raw float bits order directly; vocab idx in low 12 bits
__device__ __forceinline__ uint32_t fkey(float sb, int n) {
    return (__float_as_uint(sb) & 0xFFFFF000u) | (uint32_t)n;
}

// within a 32-k block: lane t's 16B covers both k16 groups (proven layout)
__device__ __forceinline__ int perm32(int k) {
    return ((k & 7) >> 1) * 8 + ((k >> 4) & 1) * 4 + ((k >> 3) & 1) * 2 + (k & 1);
}

// ---------------------------------------------------------------------------
// fused prep: blocks [0,512) convert vocab (+v2); blocks [512,...) patchify
// ---------------------------------------------------------------------------
__global__ void prep_kernel(const float* __restrict__ vocab,
                            const float* __restrict__ images,
                            float* __restrict__ patches) {
    if (blockIdx.x < 512) {
        const int v = blockIdx.x * 8 + (threadIdx.x >> 5);
        const int lane = threadIdx.x & 31;
        const float* row = vocab + (size_t)v * D_DIM;
        float s = 0.f;
#pragma unroll
        for (int e = 0; e < 2; e++) {
            const float4 x = *(const float4*)(row + lane * 8 + e * 4);
            s += x.x * x.x + x.y * x.y + x.z * x.z + x.w * x.w;
            const int d0 = lane * 8 + e * 4;
#pragma unroll
            for (int q = 0; q < 4; q++) {
                const int d = d0 + q;
                const float xv = q == 0 ? x.x : q == 1 ? x.y : q == 2 ? x.z : x.w;
                g_vb[v * D_DIM + (d & ~31) + perm32(d & 31)] = __float2bfloat16_rn(xv);
            }
        }
#pragma unroll
        for (int o = 16; o > 0; o >>= 1) s += __shfl_xor_sync(0xffffffffu, s, o);
        if (lane == 0) g_v2[v] = s;
    } else {
        const int idx = (blockIdx.x - 512) * 256 + threadIdx.x;
        const int d = idx & 255, n = (idx >> 8) & 255, b = idx >> 16;
        const int ph = n >> 4, pw = n & 15, i = d >> 4, j = d & 15;
        const float x = images[(b << 16) + ((ph * 16 + i) << 8) + pw * 16 + j];
        patches[idx] = x;
        g_pb[(idx & ~255) + (d & ~31) + perm32(d & 31)] = __float2bfloat16_rn(x);
    }
}

// ---------------------------------------------------------------------------
// vq: bf16 mma, vocab tile resident, 3-stage A pipeline, half-CTA barriers,
//     best1 per 16-col group (t-pair merge), biased keys   [R13 proven]
// ---------------------------------------------------------------------------
__global__ __launch_bounds__(512, 1)
void vq_kernel() {
    extern __shared__ char sm[];
    const uint32_t smem = (uint32_t)__cvta_generic_to_shared(sm);
    const uint32_t smA = smem + B_BYTES;

    const int tid  = threadIdx.x;
    const int lane = tid & 31;
    const int wid  = tid >> 5;
    const int g    = lane >> 2;
    const int t    = lane & 3;
    const int wm   = wid >> 3;           // warps 0-7 rows 0-31 (they also WRITE those rows)
    const int wn   = wid & 7;            // 8 n-warps (32 vocab cols)

    const int vt  = blockIdx.x & 15;
    const int grp = blockIdx.x >> 4;
    const int c0  = (grp * NCHUNK) / NGRP;
    const int c1  = ((grp + 1) * NCHUNK) / NGRP;

    // ---- prologue: resident B tile + A chunk c0 (one commit group) ----
    {
        const int rB = tid >> 1, hB = tid & 1;
        const __nv_bfloat16* srcB = g_vb + (size_t)(vt * VTN + rB) * D_DIM + hB * 128;
        const uint32_t dB = smem + rB * 512;
        const uint32_t swB = (uint32_t)(rB & 7) << 2;
#pragma unroll
        for (int uu = 0; uu < 16; uu++) {
            const int u = hB * 16 + uu;
            CP_ASYNC16(dB + (((uint32_t)u ^ swB) << 4), srcB + uu * 8);
        }
        const int rA = tid >> 3, qA = tid & 7;   // warp w writes rows 4w..4w+3
        const __nv_bfloat16* srcA = g_pb + (size_t)(c0 * CHM + rA) * D_DIM + qA * 32;
        const uint32_t swA = (uint32_t)(rA & 7) << 2;
#pragma unroll
        for (int uu = 0; uu < 4; uu++) {
            const int u = qA * 4 + uu;
            CP_ASYNC16(smA + rA * 512 + (((uint32_t)u ^ swA) << 4), srcA + uu * 8);
        }
        CP_COMMIT();
    }

    // biased v2 for owned columns
    float v2b[8];
#pragma unroll
    for (int j = 0; j < 4; j++)
#pragma unroll
        for (int e = 0; e < 2; e++)
            v2b[j * 2 + e] = __ldg(g_v2 + vt * VTN + wn * 32 + j * 8 + 2 * t + e) + BIAS;

    const int gi = vt * 16 + wn * 2 + (t >> 1);     // merged group index (16-col groups)
    const int barid = 1 + wm;                        // half-CTA named barrier

    // full-CTA sync once: B tile written by everyone, read by everyone
    asm volatile("cp.async.wait_group 0;" ::: "memory");
    __syncthreads();

    int s_nxt = 1;                  // stage of chunk c+1
#pragma unroll 1
    for (int c = c0; c < c1; c++) {
        const int s_cur = (s_nxt + 2) % 3;
        if (c + 1 < c1) {
            const int rA = tid >> 3, qA = tid & 7;
            const __nv_bfloat16* srcA = g_pb + (size_t)((c + 1) * CHM + rA) * D_DIM + qA * 32;
            const uint32_t dA = smA + s_nxt * A_STAGE + rA * 512;
            const uint32_t swA = (uint32_t)(rA & 7) << 2;
#pragma unroll
            for (int uu = 0; uu < 4; uu++) {
                const int u = qA * 4 + uu;
                CP_ASYNC16(dA + (((uint32_t)u ^ swA) << 4), srcA + uu * 8);
            }
            CP_COMMIT();
            asm volatile("cp.async.wait_group 1;" ::: "memory");
        } else {
            asm volatile("cp.async.wait_group 0;" ::: "memory");
        }
        // half-CTA barrier: writers of rows [wm*32, wm*32+32) == readers of same
        asm volatile("bar.sync %0, %1;" :: "r"(barid), "r"(256) : "memory");

        const char* Ab = sm + B_BYTES + s_cur * A_STAGE;
        float acc[2][4][4];
#pragma unroll
        for (int i = 0; i < 2; i++)
#pragma unroll
            for (int j = 0; j < 4; j++)
#pragma unroll
                for (int e = 0; e < 4; e++) acc[i][j][e] = 0.f;

#pragma unroll
        for (int kb = 0; kb < 8; kb++) {
            const uint32_t aoff = (uint32_t)((((kb ^ g) << 2) | t) << 4);
            uint4 af[2][2];
#pragma unroll
            for (int i = 0; i < 2; i++)
#pragma unroll
                for (int h = 0; h < 2; h++)
                    af[i][h] = *(const uint4*)(Ab + (wm * 32 + i * 16 + h * 8 + g) * 512 + aoff);
#pragma unroll
            for (int j = 0; j < 4; j++) {
                const int n = wn * 32 + j * 8 + g;      // n & 7 == g
                const uint4 bf = *(const uint4*)(sm + n * 512 + aoff);
#pragma unroll
                for (int i = 0; i < 2; i++) {
                    float* cacc = acc[i][j];
                    mma16(cacc, af[i][0].x, af[i][1].x, af[i][0].y, af[i][1].y, bf.x, bf.y);
                    mma16(cacc, af[i][0].z, af[i][1].z, af[i][0].w, af[i][1].w, bf.z, bf.w);
                }
            }
        }

        // epilogue: per-lane best1 over 8 cols per row-slot, then t-pair merge
        uint32_t k1[4];
#pragma unroll
        for (int sl = 0; sl < 4; sl++) k1[sl] = ~0u;
#pragma unroll
        for (int j = 0; j < 4; j++) {
            const int nn = vt * VTN + wn * 32 + j * 8 + 2 * t;
#pragma unroll
            for (int i = 0; i < 2; i++) {
                const uint32_t ka = min(fkey(fmaf(acc[i][j][0], -2.f, v2b[j * 2 + 0]), nn),
                                        fkey(fmaf(acc[i][j][1], -2.f, v2b[j * 2 + 1]), nn + 1));
                const uint32_t kb_ = min(fkey(fmaf(acc[i][j][2], -2.f, v2b[j * 2 + 0]), nn),
                                         fkey(fmaf(acc[i][j][3], -2.f, v2b[j * 2 + 1]), nn + 1));
                k1[i * 2 + 0] = min(k1[i * 2 + 0], ka);
                k1[i * 2 + 1] = min(k1[i * 2 + 1], kb_);
            }
        }
#pragma unroll
        for (int sl = 0; sl < 4; sl++)
            k1[sl] = min(k1[sl], __shfl_xor_sync(0xffffffffu, k1[sl], 1));
        if ((t & 1) == 0) {
#pragma unroll
            for (int i = 0; i < 2; i++)
#pragma unroll
                for (int h = 0; h < 2; h++) {
                    const int row = c * CHM + wm * 32 + i * 16 + h * 8 + g;
                    g_cand[(size_t)row * 256 + gi] = k1[i * 2 + h];
                }
        }

        s_nxt = s_nxt + 1 == 3 ? 0 : s_nxt + 1;
    }
}

// ---------------------------------------------------------------------------
// exact fp32 rescue: one WARP per patch, 256 coalesced best1 keys, coop dots
// ---------------------------------------------------------------------------
__global__ __launch_bounds__(512)
void rescue_kernel(const float* __restrict__ patches,
                   const float* __restrict__ vocab,
                   float* __restrict__ tokens) {
    const int p    = (blockIdx.x * 512 + threadIdx.x) >> 5;
    const int lane = threadIdx.x & 31;
    if (p >= NPATCH) return;

    const uint4* cp4 = (const uint4*)(g_cand + (size_t)p * 256);   // 64 uint4
    const uint4 kk0 = cp4[lane];
    const uint4 kk1 = cp4[32 + lane];
    const uint32_t keys[8] = {kk0.x, kk0.y, kk0.z, kk0.w, kk1.x, kk1.y, kk1.z, kk1.w};

    uint32_t kmin = ~0u;
#pragma unroll
    for (int r = 0; r < 8; r++) kmin = min(kmin, keys[r]);
#pragma unroll
    for (int o = 16; o > 0; o >>= 1)
        kmin = min(kmin, __shfl_xor_sync(0xffffffffu, kmin, o));
    const float fthr = __uint_as_float(kmin & 0xFFFFF000u) + THR;
    const uint32_t thrk = __float_as_uint(fthr) | 0xFFFu;

    const float* pp = patches + (size_t)p * D_DIM;
    const float4 pa = *(const float4*)(pp + lane * 8);
    const float4 pb = *(const float4*)(pp + lane * 8 + 4);

    float bestv = 3.4e38f;
    int   besti = 0x7FFFFFFF;
#pragma unroll
    for (int r = 0; r < 8; r++) {
        unsigned mask = __ballot_sync(0xffffffffu, keys[r] <= thrk);
        while (mask) {
            const int src = __ffs(mask) - 1;
            mask &= mask - 1;
            const int vi = (int)(__shfl_sync(0xffffffffu, keys[r], src) & 0xFFFu);
            const float* vp = vocab + (size_t)vi * D_DIM;
            const float4 va = *(const float4*)(vp + lane * 8);
            const float4 vb = *(const float4*)(vp + lane * 8 + 4);
            float d = pa.x * va.x + pa.y * va.y + pa.z * va.z + pa.w * va.w
                    + pb.x * vb.x + pb.y * vb.y + pb.z * vb.z + pb.w * vb.w;
#pragma unroll
            for (int o = 16; o > 0; o >>= 1)
                d += __shfl_xor_sync(0xffffffffu, d, o);
            const float se = __ldg(&g_v2[vi]) - 2.f * d;
            if (se < bestv || (se == bestv && vi < besti)) { bestv = se; besti = vi; }
        }
    }
    if (lane == 0) tokens[p] = (float)besti;
}

// ---------------------------------------------------------------------------
extern "C" void kernel_launch(void* const* d_in, const int* in_sizes, int n_in,
                              void* d_out, int out_size) {
    const float* images = (const float*)d_in[0];   // [64, 256, 256]
    const float* vocab  = (const float*)d_in[1];   // [4096, 256]
    float* out = (float*)d_out;

    const int npix = in_sizes[0];                  // 4194304

    float* patches = out;
    float* tokens  = out + npix;

    prep_kernel<<<512 + npix / 256, 256>>>(vocab, images, patches);

    cudaFuncSetAttribute(vq_kernel, cudaFuncAttributeMaxDynamicSharedMemorySize, SMEM_BYTES);
    vq_kernel<<<NVT * NGRP, 512, SMEM_BYTES>>>();

    rescue_kernel<<<NPATCH / 16, 512>>>(patches, vocab, tokens);
}

// round 16
// speedup vs baseline: 1.0519x; 1.0161x over previous
#include <cuda_runtime.h>
#include <cuda_bf16.h>
#include <cstdint>

#define D_DIM   256
#define NPATCH  16384
#define VOCAB   4096

#define NVT     16          // vocab tiles of 256 rows
#define VTN     256
#define CHM     64          // patches per chunk
#define NGRP    9           // grid = 144
#define NCHUNK  (NPATCH / CHM)   // 256

#define B_BYTES (VTN * 512)              // 131072 (vocab tile bf16, full K)
#define A_STAGE (CHM * 512)              // 32768
#define SMEM_BYTES (B_BYTES + 3 * A_STAGE)  // 229376

#define BIAS    512.0f
#define THR     2.5f

__device__ float         g_v2[VOCAB];
__device__ __nv_bfloat16 g_pb[NPATCH * D_DIM];
__device__ __nv_bfloat16 g_vb[VOCAB * D_DIM];
__device__ uint32_t      g_cand[(size_t)NPATCH * 256];   // [patch][vt*16+wn*2+(t>>1)] best-1 key

#define CP_ASYNC16(dst, src) \
    asm volatile("cp.async.cg.shared.global [%0], [%1], 16;" :: "r"((uint32_t)(dst)), "l"(src))
#define CP_COMMIT() asm volatile("cp.async.commit_group;" ::: "memory")

__device__ __forceinline__ void mma16(float* c, uint32_t a0, uint32_t a1, uint32_t a2, uint32_t a3,
                                      uint32_t b0, uint32_t b1) {
    asm("mma.sync.aligned.m16n8k16.row.col.f32.bf16.bf16.f32 "
        "{%0,%1,%2,%3}, {%4,%5,%6,%7}, {%8,%9}, {%0,%1,%2,%3};"
        : "+f"(c[0]), "+f"(c[1]), "+f"(c[2]), "+f"(c[3])
        : "r"(a0), "r"(a1), "r"(a2), "r"(a3), "r"(b0), "r"(b1));
}

// biased-positive key: raw float bits order directly; vocab idx in low 12 bits
__device__ __forceinline__ uint32_t fkey(float sb, int n) {
    return (__float_as_uint(sb) & 0xFFFFF000u) | (uint32_t)n;
}

__device__ __forceinline__ uint32_t bfpack(float lo, float hi) {
    const uint32_t l = __bfloat16_as_ushort(__float2bfloat16_rn(lo));
    const uint32_t h = __bfloat16_as_ushort(__float2bfloat16_rn(hi));
    return l | (h << 16);
}

// ---------------------------------------------------------------------------
// fused prep, 8 elements/thread, paired 4B permuted stores.
// blocks [0,512): vocab (+v2), one warp per row; blocks [512,...): patchify
// ---------------------------------------------------------------------------
__global__ void prep_kernel(const float* __restrict__ vocab,
                            const float* __restrict__ images,
                            float* __restrict__ patches) {
    if (blockIdx.x < 512) {
        const int v = blockIdx.x * 8 + (threadIdx.x >> 5);
        const int lane = threadIdx.x & 31;
        const int d0 = lane * 8;
        const float4 xa = *(const float4*)(vocab + (size_t)v * D_DIM + d0);
        const float4 xb = *(const float4*)(vocab + (size_t)v * D_DIM + d0 + 4);
        float s = xa.x * xa.x + xa.y * xa.y + xa.z * xa.z + xa.w * xa.w
                + xb.x * xb.x + xb.y * xb.y + xb.z * xb.z + xb.w * xb.w;
        const uint32_t pk[4] = {bfpack(xa.x, xa.y), bfpack(xa.z, xa.w),
                                bfpack(xb.x, xb.y), bfpack(xb.z, xb.w)};
        uint16_t* dst = (uint16_t*)g_vb + v * D_DIM + (d0 & ~31);
        const int q2 = (d0 & 31) >> 2;
#pragma unroll
        for (int m = 0; m < 4; m++)
            *(uint32_t*)(dst + m * 8 + q2) = pk[m];
#pragma unroll
        for (int o = 16; o > 0; o >>= 1) s += __shfl_xor_sync(0xffffffffu, s, o);
        if (lane == 0) g_v2[v] = s;
    } else {
        const int idx0 = (blockIdx.x - 512) * 2048 + threadIdx.x * 8;
        const int d0 = idx0 & 255, n = (idx0 >> 8) & 255, b = idx0 >> 16;
        const int ph = n >> 4, pw = n & 15, i = d0 >> 4, j = d0 & 15;   // j in {0,8}
        const float* src = images + (b << 16) + ((ph * 16 + i) << 8) + pw * 16 + j;
        const float4 xa = *(const float4*)(src);
        const float4 xb = *(const float4*)(src + 4);
        *(float4*)(patches + idx0) = xa;
        *(float4*)(patches + idx0 + 4) = xb;
        const uint32_t pk[4] = {bfpack(xa.x, xa.y), bfpack(xa.z, xa.w),
                                bfpack(xb.x, xb.y), bfpack(xb.z, xb.w)};
        uint16_t* dst = (uint16_t*)g_pb + (idx0 & ~31);
        const int q2 = (d0 & 31) >> 2;
#pragma unroll
        for (int m = 0; m < 4; m++)
            *(uint32_t*)(dst + m * 8 + q2) = pk[m];
    }
}

// ---------------------------------------------------------------------------
// vq: bf16 mma, vocab tile resident, 3-stage A pipeline, half-CTA barriers,
//     best1 per 16-col group (t-pair merge), biased keys   [R13/R15 proven]
// ---------------------------------------------------------------------------
__global__ __launch_bounds__(512, 1)
void vq_kernel() {
    extern __shared__ char sm[];
    const uint32_t smem = (uint32_t)__cvta_generic_to_shared(sm);
    const uint32_t smA = smem + B_BYTES;

    const int tid  = threadIdx.x;
    const int lane = tid & 31;
    const int wid  = tid >> 5;
    const int g    = lane >> 2;
    const int t    = lane & 3;
    const int wm   = wid >> 3;           // warps 0-7 rows 0-31 (they also WRITE those rows)
    const int wn   = wid & 7;            // 8 n-warps (32 vocab cols)

    const int vt  = blockIdx.x & 15;
    const int grp = blockIdx.x >> 4;
    const int c0  = (grp * NCHUNK) / NGRP;
    const int c1  = ((grp + 1) * NCHUNK) / NGRP;

    // ---- prologue: resident B tile + A chunk c0 (one commit group) ----
    {
        const int rB = tid >> 1, hB = tid & 1;
        const __nv_bfloat16* srcB = g_vb + (size_t)(vt * VTN + rB) * D_DIM + hB * 128;
        const uint32_t dB = smem + rB * 512;
        const uint32_t swB = (uint32_t)(rB & 7) << 2;
#pragma unroll
        for (int uu = 0; uu < 16; uu++) {
            const int u = hB * 16 + uu;
            CP_ASYNC16(dB + (((uint32_t)u ^ swB) << 4), srcB + uu * 8);
        }
        const int rA = tid >> 3, qA = tid & 7;   // warp w writes rows 4w..4w+3
        const __nv_bfloat16* srcA = g_pb + (size_t)(c0 * CHM + rA) * D_DIM + qA * 32;
        const uint32_t swA = (uint32_t)(rA & 7) << 2;
#pragma unroll
        for (int uu = 0; uu < 4; uu++) {
            const int u = qA * 4 + uu;
            CP_ASYNC16(smA + rA * 512 + (((uint32_t)u ^ swA) << 4), srcA + uu * 8);
        }
        CP_COMMIT();
    }

    // biased v2 for owned columns
    float v2b[8];
#pragma unroll
    for (int j = 0; j < 4; j++)
#pragma unroll
        for (int e = 0; e < 2; e++)
            v2b[j * 2 + e] = __ldg(g_v2 + vt * VTN + wn * 32 + j * 8 + 2 * t + e) + BIAS;

    const int gi = vt * 16 + wn * 2 + (t >> 1);     // merged group index (16-col groups)
    const int barid = 1 + wm;                        // half-CTA named barrier

    // full-CTA sync once: B tile written by everyone, read by everyone
    asm volatile("cp.async.wait_group 0;" ::: "memory");
    __syncthreads();

    int s_nxt = 1;                  // stage of chunk c+1
#pragma unroll 1
    for (int c = c0; c < c1; c++) {
        const int s_cur = (s_nxt + 2) % 3;
        if (c + 1 < c1) {
            const int rA = tid >> 3, qA = tid & 7;
            const __nv_bfloat16* srcA = g_pb + (size_t)((c + 1) * CHM + rA) * D_DIM + qA * 32;
            const uint32_t dA = smA + s_nxt * A_STAGE + rA * 512;
            const uint32_t swA = (uint32_t)(rA & 7) << 2;
#pragma unroll
            for (int uu = 0; uu < 4; uu++) {
                const int u = qA * 4 + uu;
                CP_ASYNC16(dA + (((uint32_t)u ^ swA) << 4), srcA + uu * 8);
            }
            CP_COMMIT();
            asm volatile("cp.async.wait_group 1;" ::: "memory");
        } else {
            asm volatile("cp.async.wait_group 0;" ::: "memory");
        }
        // half-CTA barrier: writers of rows [wm*32, wm*32+32) == readers of same
        asm volatile("bar.sync %0, %1;" :: "r"(barid), "r"(256) : "memory");

        const char* Ab = sm + B_BYTES + s_cur * A_STAGE;
        float acc[2][4][4];
#pragma unroll
        for (int i = 0; i < 2; i++)
#pragma unroll
            for (int j = 0; j < 4; j++)
#pragma unroll
                for (int e = 0; e < 4; e++) acc[i][j][e] = 0.f;

#pragma unroll
        for (int kb = 0; kb < 8; kb++) {
            const uint32_t aoff = (uint32_t)((((kb ^ g) << 2) | t) << 4);
            uint4 af[2][2];
#pragma unroll
            for (int i = 0; i < 2; i++)
#pragma unroll
                for (int h = 0; h < 2; h++)
                    af[i][h] = *(const uint4*)(Ab + (wm * 32 + i * 16 + h * 8 + g) * 512 + aoff);
#pragma unroll
            for (int j = 0; j < 4; j++) {
                const int n = wn * 32 + j * 8 + g;      // n & 7 == g
                const uint4 bf = *(const uint4*)(sm + n * 512 + aoff);
#pragma unroll
                for (int i = 0; i < 2; i++) {
                    float* cacc = acc[i][j];
                    mma16(cacc, af[i][0].x, af[i][1].x, af[i][0].y, af[i][1].y, bf.x, bf.y);
                    mma16(cacc, af[i][0].z, af[i][1].z, af[i][0].w, af[i][1].w, bf.z, bf.w);
                }
            }
        }

        // epilogue: per-lane best1 over 8 cols per row-slot, then t-pair merge
        uint32_t k1[4];
#pragma unroll
        for (int sl = 0; sl < 4; sl++) k1[sl] = ~0u;
#pragma unroll
        for (int j = 0; j < 4; j++) {
            const int nn = vt * VTN + wn * 32 + j * 8 + 2 * t;
#pragma unroll
            for (int i = 0; i < 2; i++) {
                const uint32_t ka = min(fkey(fmaf(acc[i][j][0], -2.f, v2b[j * 2 + 0]), nn),
                                        fkey(fmaf(acc[i][j][1], -2.f, v2b[j * 2 + 1]), nn + 1));
                const uint32_t kb_ = min(fkey(fmaf(acc[i][j][2], -2.f, v2b[j * 2 + 0]), nn),
                                         fkey(fmaf(acc[i][j][3], -2.f, v2b[j * 2 + 1]), nn + 1));
                k1[i * 2 + 0] = min(k1[i * 2 + 0], ka);
                k1[i * 2 + 1] = min(k1[i * 2 + 1], kb_);
            }
        }
#pragma unroll
        for (int sl = 0; sl < 4; sl++)
            k1[sl] = min(k1[sl], __shfl_xor_sync(0xffffffffu, k1[sl], 1));
        if ((t & 1) == 0) {
#pragma unroll
            for (int i = 0; i < 2; i++)
#pragma unroll
                for (int h = 0; h < 2; h++) {
                    const int row = c * CHM + wm * 32 + i * 16 + h * 8 + g;
                    g_cand[(size_t)row * 256 + gi] = k1[i * 2 + h];
                }
        }

        s_nxt = s_nxt + 1 == 3 ? 0 : s_nxt + 1;
    }
}

// ---------------------------------------------------------------------------
// exact fp32 rescue: one WARP per patch, 256 coalesced best1 keys, coop dots
// ---------------------------------------------------------------------------
__global__ __launch_bounds__(512)
void rescue_kernel(const float* __restrict__ patches,
                   const float* __restrict__ vocab,
                   float* __restrict__ tokens) {
    const int p    = (blockIdx.x * 512 + threadIdx.x) >> 5;
    const int lane = threadIdx.x & 31;
    if (p >= NPATCH) return;

    const uint4* cp4 = (const uint4*)(g_cand + (size_t)p * 256);   // 64 uint4
    const uint4 kk0 = cp4[lane];
    const uint4 kk1 = cp4[32 + lane];
    const uint32_t keys[8] = {kk0.x, kk0.y, kk0.z, kk0.w, kk1.x, kk1.y, kk1.z, kk1.w};

    uint32_t kmin = ~0u;
#pragma unroll
    for (int r = 0; r < 8; r++) kmin = min(kmin, keys[r]);
#pragma unroll
    for (int o = 16; o > 0; o >>= 1)
        kmin = min(kmin, __shfl_xor_sync(0xffffffffu, kmin, o));
    const float fthr = __uint_as_float(kmin & 0xFFFFF000u) + THR;
    const uint32_t thrk = __float_as_uint(fthr) | 0xFFFu;

    const float* pp = patches + (size_t)p * D_DIM;
    const float4 pa = *(const float4*)(pp + lane * 8);
    const float4 pb = *(const float4*)(pp + lane * 8 + 4);

    float bestv = 3.4e38f;
    int   besti = 0x7FFFFFFF;
#pragma unroll
    for (int r = 0; r < 8; r++) {
        unsigned mask = __ballot_sync(0xffffffffu, keys[r] <= thrk);
        while (mask) {
            const int src = __ffs(mask) - 1;
            mask &= mask - 1;
            const int vi = (int)(__shfl_sync(0xffffffffu, keys[r], src) & 0xFFFu);
            const float* vp = vocab + (size_t)vi * D_DIM;
            const float4 va = *(const float4*)(vp + lane * 8);
            const float4 vb = *(const float4*)(vp + lane * 8 + 4);
            float d = pa.x * va.x + pa.y * va.y + pa.z * va.z + pa.w * va.w
                    + pb.x * vb.x + pb.y * vb.y + pb.z * vb.z + pb.w * vb.w;
#pragma unroll
            for (int o = 16; o > 0; o >>= 1)
                d += __shfl_xor_sync(0xffffffffu, d, o);
            const float se = __ldg(&g_v2[vi]) - 2.f * d;
            if (se < bestv || (se == bestv && vi < besti)) { bestv = se; besti = vi; }
        }
    }
    if (lane == 0) tokens[p] = (float)besti;
}

// ---------------------------------------------------------------------------
extern "C" void kernel_launch(void* const* d_in, const int* in_sizes, int n_in,
                              void* d_out, int out_size) {
    const float* images = (const float*)d_in[0];   // [64, 256, 256]
    const float* vocab  = (const float*)d_in[1];   // [4096, 256]
    float* out = (float*)d_out;

    const int npix = in_sizes[0];                  // 4194304

    float* patches = out;
    float* tokens  = out + npix;

    prep_kernel<<<512 + npix / 2048, 256>>>(vocab, images, patches);

    cudaFuncSetAttribute(vq_kernel, cudaFuncAttributeMaxDynamicSharedMemorySize, SMEM_BYTES);
    vq_kernel<<<NVT * NGRP, 512, SMEM_BYTES>>>();

    rescue_kernel<<<NPATCH / 16, 512>>>(patches, vocab, tokens);
}